// round 16
// baseline (speedup 1.0000x reference)
#include <cuda_runtime.h>

#define DD 128
#define HH 160
#define WW 160
#define W4 40                      // WW / 4
#define HWX (HH * WW)              // 25600
#define HW4 (HH * W4)              // 6400 float4 per slice
#define NV  (DD * HWX)             // 3276800
#define NV4 (DD * HW4)             // 819200 float4 per channel
#define NITER 10

// Gaussian weights: exp(-x^2/2), x in [-2,2], normalized
#define GW0 0.40261995f
#define GW1 0.24420134f
#define GW2 0.05448868f

// Scratch (device globals: allocation-free). In-place force: no vfB.
static __device__ float g_sum[NV];
static __device__ float g_vfA[3 * NV];
static __device__ float g_vfC[3 * NV];

// ---------------------------------------------------------------------------
// Warp pass, row-per-warp layout, 3-phase, BRANCHLESS gather:
// clamp corner indices (safe addresses) and fold bounds masks into lerp
// weights -> all 40 gather loads are unconditional (max MLP, no divergence).
// ---------------------------------------------------------------------------
__global__ void __launch_bounds__(256) warp_kernel_row(const float* __restrict__ mov,
                                                       const float* __restrict__ fix,
                                                       const float* __restrict__ vf,
                                                       float* __restrict__ sum) {
    int gwarp = (blockIdx.x * 256 + threadIdx.x) >> 5;   // row id (uniform per warp)
    int lane  = threadIdx.x & 31;
    if (gwarp >= DD * HH) return;
    int d = gwarp / HH;          // warp-uniform
    int h = gwarp - d * HH;
    int rowbase = gwarp * WW;

    // Phase 1: batched coalesced loads (20 outstanding)
    float vd[5], vh[5], vw[5], fxv[5];
    #pragma unroll
    for (int j = 0; j < 5; ++j) {
        int i = rowbase + lane + j * 32;
        vd[j]  = __ldg(vf + i);
        vh[j]  = __ldg(vf + NV + i);
        vw[j]  = __ldg(vf + 2 * NV + i);
        fxv[j] = __ldg(fix + i);
    }

    // Phase 2: coordinate math
    float td[5], th[5], tw[5];
    int   d0[5], h0[5], w0[5];
    #pragma unroll
    for (int j = 0; j < 5; ++j) {
        float cd = (float)d + vd[j];
        float ch = (float)h + vh[j];
        float cw = (float)(lane + j * 32) + vw[j];
        d0[j] = __float2int_rd(cd);
        h0[j] = __float2int_rd(ch);
        w0[j] = __float2int_rd(cw);
        td[j] = cd - (float)d0[j];
        th[j] = ch - (float)h0[j];
        tw[j] = cw - (float)w0[j];
    }

    // Phase 3: branchless gathers
    float res[5];
    #pragma unroll
    for (int j = 0; j < 5; ++j) {
        // masks (cval = 0 outside)
        float mw0 = ((unsigned)w0[j]       < WW) ? 1.f : 0.f;
        float mw1 = ((unsigned)(w0[j] + 1) < WW) ? 1.f : 0.f;
        float mh0 = ((unsigned)h0[j]       < HH) ? 1.f : 0.f;
        float mh1 = ((unsigned)(h0[j] + 1) < HH) ? 1.f : 0.f;
        float md0 = ((unsigned)d0[j]       < DD) ? 1.f : 0.f;
        float md1 = ((unsigned)(d0[j] + 1) < DD) ? 1.f : 0.f;

        // clamped indices (always-valid addresses)
        int wc0 = min(max(w0[j], 0), WW - 1);
        int wc1 = min(max(w0[j] + 1, 0), WW - 1);
        int hc0 = min(max(h0[j], 0), HH - 1);
        int hc1 = min(max(h0[j] + 1, 0), HH - 1);
        int dc0 = min(max(d0[j], 0), DD - 1);
        int dc1 = min(max(d0[j] + 1, 0), DD - 1);

        const float* r00 = mov + (dc0 * HH + hc0) * WW;
        const float* r01 = mov + (dc0 * HH + hc1) * WW;
        const float* r10 = mov + (dc1 * HH + hc0) * WW;
        const float* r11 = mov + (dc1 * HH + hc1) * WW;

        float m000 = __ldg(r00 + wc0), m001 = __ldg(r00 + wc1);
        float m010 = __ldg(r01 + wc0), m011 = __ldg(r01 + wc1);
        float m100 = __ldg(r10 + wc0), m101 = __ldg(r10 + wc1);
        float m110 = __ldg(r11 + wc0), m111 = __ldg(r11 + wc1);

        // masked lerp weights
        float twl = (1.f - tw[j]) * mw0, twr = tw[j] * mw1;
        float thl = (1.f - th[j]) * mh0, thr = th[j] * mh1;
        float tdl = (1.f - td[j]) * md0, tdr = td[j] * md1;

        float c00 = m000 * twl + m001 * twr;
        float c01 = m010 * twl + m011 * twr;
        float c10 = m100 * twl + m101 * twr;
        float c11 = m110 * twl + m111 * twr;
        res[j] = (c00 * thl + c01 * thr) * tdl + (c10 * thl + c11 * thr) * tdr;
    }

    #pragma unroll
    for (int j = 0; j < 5; ++j)
        sum[rowbase + lane + j * 32] = res[j] + fxv[j];
}

// ---------------------------------------------------------------------------
// Shared demons math
// ---------------------------------------------------------------------------
__device__ __forceinline__ void demons_update(
    int w4, int h, int d,
    float4 sm, float4 sl, float4 sr, float4 su, float4 sd, float4 sf, float4 sb,
    float4 fx, float4 v0, float4 v1, float4 v2,
    float4& o0, float4& o1, float4& o2)
{
    #pragma unroll
    for (int j = 0; j < 4; ++j) {
        int w = w4 * 4 + j;
        float smj = ((const float*)&sm)[j];

        float left  = (j > 0) ? ((const float*)&sm)[j-1] : sl.w;
        float right = (j < 3) ? ((const float*)&sm)[j+1] : sr.x;
        float g2 = (w == 0) ? (right - smj) : (w == WW-1) ? (smj - left) : 0.5f * (right - left);

        float up = ((const float*)&su)[j], dn = ((const float*)&sd)[j];
        float g1 = (h == 0) ? (dn - smj) : (h == HH-1) ? (smj - up) : 0.5f * (dn - up);

        float fr = ((const float*)&sf)[j], bk = ((const float*)&sb)[j];
        float g0 = (d == 0) ? (bk - smj) : (d == DD-1) ? (smj - fr) : 0.5f * (bk - fr);

        float dv = smj - 2.0f * ((const float*)&fx)[j];   // warped - fix
        float denom = g0*g0 + g1*g1 + g2*g2 + dv*dv;
        float scale = (denom > 1e-6f) ? __fdividef(-dv, denom) : 0.0f;

        ((float*)&o0)[j] = ((const float*)&v0)[j] + scale * g0;
        ((float*)&o1)[j] = ((const float*)&v1)[j] + scale * g1;
        ((float*)&o2)[j] = ((const float*)&v2)[j] + scale * g2;
    }
}

// ---------------------------------------------------------------------------
// Force (iterations >= 1): IN-PLACE vf update (center-only vf access — safe).
// ---------------------------------------------------------------------------
__global__ void __launch_bounds__(256) force_kernel4(const float4* __restrict__ s,
                                                     const float4* __restrict__ fix,
                                                     float4* __restrict__ vf) {
    int i4 = blockIdx.x * 256 + threadIdx.x;
    if (i4 >= NV4) return;
    int w4 = i4 % W4;
    int h  = (i4 / W4) % HH;
    int d  = i4 / HW4;

    const float4 z4 = make_float4(0.f, 0.f, 0.f, 0.f);
    float4 fx = fix[i4];
    float4 v0 = vf[i4], v1 = vf[NV4 + i4], v2 = vf[2 * NV4 + i4];
    float4 sm = s[i4];
    float4 sl = (w4 > 0)      ? s[i4 - 1]   : z4;
    float4 sr = (w4 < W4 - 1) ? s[i4 + 1]   : z4;
    float4 su = (h  > 0)      ? s[i4 - W4]  : z4;
    float4 sd = (h  < HH - 1) ? s[i4 + W4]  : z4;
    float4 sf = (d  > 0)      ? s[i4 - HW4] : z4;
    float4 sb = (d  < DD - 1) ? s[i4 + HW4] : z4;

    float4 o0, o1, o2;
    demons_update(w4, h, d, sm, sl, sr, su, sd, sf, sb, fx, v0, v1, v2, o0, o1, o2);

    vf[i4]           = o0;
    vf[NV4 + i4]     = o1;
    vf[2 * NV4 + i4] = o2;
}

// ---------------------------------------------------------------------------
// Force iteration 0: vf == 0, warped == mov; sum computed inline from inputs.
// ---------------------------------------------------------------------------
__global__ void __launch_bounds__(256) force0_kernel4(const float4* __restrict__ mov,
                                                      const float4* __restrict__ fix,
                                                      float4* __restrict__ vf_out) {
    int i4 = blockIdx.x * 256 + threadIdx.x;
    if (i4 >= NV4) return;
    int w4 = i4 % W4;
    int h  = (i4 / W4) % HH;
    int d  = i4 / HW4;

    const float4 z4 = make_float4(0.f, 0.f, 0.f, 0.f);
    #define SUMLD(off) make_float4(mov[off].x + fix[off].x, mov[off].y + fix[off].y, \
                                   mov[off].z + fix[off].z, mov[off].w + fix[off].w)
    float4 sm = SUMLD(i4);
    float4 sl = (w4 > 0)      ? SUMLD(i4 - 1)   : z4;
    float4 sr = (w4 < W4 - 1) ? SUMLD(i4 + 1)   : z4;
    float4 su = (h  > 0)      ? SUMLD(i4 - W4)  : z4;
    float4 sd = (h  < HH - 1) ? SUMLD(i4 + W4)  : z4;
    float4 sf = (d  > 0)      ? SUMLD(i4 - HW4) : z4;
    float4 sb = (d  < DD - 1) ? SUMLD(i4 + HW4) : z4;
    #undef SUMLD
    float4 fx = fix[i4];

    float4 o0, o1, o2;
    demons_update(w4, h, d, sm, sl, sr, su, sd, sf, sb, fx, z4, z4, z4, o0, o1, o2);

    vf_out[i4]           = o0;
    vf_out[NV4 + i4]     = o1;
    vf_out[2 * NV4 + i4] = o2;
}

// ---------------------------------------------------------------------------
// Fused W+H Gaussian smoothing, single smem buffer.
// ---------------------------------------------------------------------------
#define TROWS 36
#define IROWS 32
#define NT_HW 5   // 160 / 32

__global__ void __launch_bounds__(256) smoothHW_kernel(const float4* __restrict__ in,
                                                       float4* __restrict__ out) {
    __shared__ float4 s1[TROWS * W4];

    int b  = blockIdx.x;
    int ht = b % NT_HW;
    int d  = (b / NT_HW) % DD;
    int c  = b / (NT_HW * DD);
    int h0 = ht * IROWS;

    const float4* src = in  + (size_t)c * NV4 + (size_t)d * HW4;
    float4*       dst = out + (size_t)c * NV4 + (size_t)d * HW4;
    const float4 z4 = make_float4(0.f, 0.f, 0.f, 0.f);

    for (int t = threadIdx.x; t < TROWS * W4; t += 256) {
        int r  = t / W4;
        int cc = t % W4;
        int hg = h0 - 2 + r;
        float4 o;
        if ((unsigned)hg < HH) {
            const float4* row = src + hg * W4;
            float4 m = __ldg(row + cc);
            float4 l = (cc > 0)      ? __ldg(row + cc - 1) : z4;
            float4 r2 = (cc < W4 - 1) ? __ldg(row + cc + 1) : z4;
            o.x = GW2*l.z + GW1*l.w + GW0*m.x + GW1*m.y + GW2*m.z;
            o.y = GW2*l.w + GW1*m.x + GW0*m.y + GW1*m.z + GW2*m.w;
            o.z = GW2*m.x + GW1*m.y + GW0*m.z + GW1*m.w + GW2*r2.x;
            o.w = GW2*m.y + GW1*m.z + GW0*m.w + GW1*r2.x + GW2*r2.y;
        } else {
            o = z4;
        }
        s1[t] = o;
    }
    __syncthreads();

    for (int t = threadIdx.x; t < IROWS * W4; t += 256) {
        int r  = t / W4 + 2;
        int cc = t % W4;
        float4 a = s1[(r - 2) * W4 + cc];
        float4 b2 = s1[(r - 1) * W4 + cc];
        float4 m = s1[r * W4 + cc];
        float4 e = s1[(r + 1) * W4 + cc];
        float4 f = s1[(r + 2) * W4 + cc];
        float4 o;
        o.x = GW2*(a.x + f.x) + GW1*(b2.x + e.x) + GW0*m.x;
        o.y = GW2*(a.y + f.y) + GW1*(b2.y + e.y) + GW0*m.y;
        o.z = GW2*(a.z + f.z) + GW1*(b2.z + e.z) + GW0*m.z;
        o.w = GW2*(a.w + f.w) + GW1*(b2.w + e.w) + GW0*m.w;
        dst[(h0 + r - 2) * W4 + cc] = o;
    }
}

// ---------------------------------------------------------------------------
// D-axis smoothing: 2 column streams per thread (2x MLP), 16 outputs each.
// ---------------------------------------------------------------------------
#define DSEG 16
#define NDSEG (DD / DSEG)   // 8
#define HALFC (HW4 / 2)     // 3200

__global__ void __launch_bounds__(256) smoothD_slide2(const float4* __restrict__ in,
                                                      float4* __restrict__ out) {
    int gid = blockIdx.x * 256 + threadIdx.x;
    int col = gid % HALFC;
    int seg = (gid / HALFC) % NDSEG;
    int c   = gid / (HALFC * NDSEG);
    const float4 z4 = make_float4(0.f, 0.f, 0.f, 0.f);

    const float4* pa = in  + (size_t)c * NV4 + col;
    const float4* pb = pa + HALFC;
    float4*       qa = out + (size_t)c * NV4 + col;
    float4*       qb = qa + HALFC;
    int d0 = seg * DSEG;

    float4 a0, a1, a2, a3, a4, b0, b1, b2, b3, b4;
    if (d0 >= 2) { a0 = pa[(size_t)(d0-2)*HW4]; b0 = pb[(size_t)(d0-2)*HW4]; }
    else         { a0 = z4; b0 = z4; }
    if (d0 >= 1) { a1 = pa[(size_t)(d0-1)*HW4]; b1 = pb[(size_t)(d0-1)*HW4]; }
    else         { a1 = z4; b1 = z4; }
    a2 = pa[(size_t)d0*HW4];     b2 = pb[(size_t)d0*HW4];
    a3 = pa[(size_t)(d0+1)*HW4]; b3 = pb[(size_t)(d0+1)*HW4];
    a4 = pa[(size_t)(d0+2)*HW4]; b4 = pb[(size_t)(d0+2)*HW4];

    #pragma unroll
    for (int dd = 0; dd < DSEG; ++dd) {
        int d = d0 + dd;
        float4 oa, ob;
        oa.x = GW2*(a0.x + a4.x) + GW1*(a1.x + a3.x) + GW0*a2.x;
        oa.y = GW2*(a0.y + a4.y) + GW1*(a1.y + a3.y) + GW0*a2.y;
        oa.z = GW2*(a0.z + a4.z) + GW1*(a1.z + a3.z) + GW0*a2.z;
        oa.w = GW2*(a0.w + a4.w) + GW1*(a1.w + a3.w) + GW0*a2.w;
        ob.x = GW2*(b0.x + b4.x) + GW1*(b1.x + b3.x) + GW0*b2.x;
        ob.y = GW2*(b0.y + b4.y) + GW1*(b1.y + b3.y) + GW0*b2.y;
        ob.z = GW2*(b0.z + b4.z) + GW1*(b1.z + b3.z) + GW0*b2.z;
        ob.w = GW2*(b0.w + b4.w) + GW1*(b1.w + b3.w) + GW0*b2.w;
        qa[(size_t)d * HW4] = oa;
        qb[(size_t)d * HW4] = ob;
        a0 = a1; a1 = a2; a2 = a3; a3 = a4;
        b0 = b1; b1 = b2; b2 = b3; b3 = b4;
        if (d + 3 < DD) {
            a4 = pa[(size_t)(d + 3) * HW4];
            b4 = pb[(size_t)(d + 3) * HW4];
        } else {
            a4 = z4; b4 = z4;
        }
    }
}

extern "C" void kernel_launch(void* const* d_in, const int* in_sizes, int n_in,
                              void* d_out, int out_size) {
    const float* mov = (const float*)d_in[0];
    const float* fixf = (const float*)d_in[1];
    const float4* fix = (const float4*)d_in[1];
    float4* out4 = (float4*)d_out;

    float *vfA, *vfC, *sum;
    cudaGetSymbolAddress((void**)&vfA, g_vfA);
    cudaGetSymbolAddress((void**)&vfC, g_vfC);
    cudaGetSymbolAddress((void**)&sum, g_sum);

    const int blocksN4  = NV4 / 256;                   // 3200
    const int blocksHW  = 3 * DD * NT_HW;              // 1920
    const int blocksD   = (3 * NDSEG * HALFC) / 256;   // 300
    const int blocksRow = (DD * HH) / 8;               // 2560 (8 warps/block)

    for (int it = 0; it < NITER; ++it) {
        if (it == 0) {
            force0_kernel4<<<blocksN4, 256>>>((const float4*)mov, fix, (float4*)vfA);
        } else {
            warp_kernel_row<<<blocksRow, 256>>>(mov, fixf, vfA, sum);
            force_kernel4<<<blocksN4, 256>>>((const float4*)sum, fix, (float4*)vfA);
        }
        smoothHW_kernel<<<blocksHW, 256>>>((const float4*)vfA, (float4*)vfC);
        float4* dst = (it == NITER - 1) ? out4 : (float4*)vfA;
        smoothD_slide2<<<blocksD, 256>>>((const float4*)vfC, dst);
    }
}